// round 16
// baseline (speedup 1.0000x reference)
#include <cuda_runtime.h>
#include <cuda_bf16.h>
#include <math.h>
#include <stdint.h>

#define BB   64
#define SS   512
#define II   512
#define HH   1024
#define G4   4096
#define OO   512
#define BH   (BB*HH)          // 65536
#define OUT_ELEMS (BB*SS*OO)  // 16777216
#define NBLK 128

typedef unsigned long long u64;

// -------- scratch (device globals; allocation-free per rules) --------
__device__ float g_xg[(size_t)SS * BB * G4];   // 512 MB, reused for both layers
__device__ float g_y [(size_t)BB * SS * HH];   // 128 MB, y0 then y1 (in place)
__device__ float g_h [2 * BH + 64];            // double-buffered hidden state
__device__ unsigned g_bar;                     // grid barrier counter

// ---------------- f32x2 helpers ----------------
__device__ __forceinline__ void fma2(u64& d, u64 a, u64 b) {
    asm("fma.rn.f32x2 %0, %1, %2, %3;" : "=l"(d) : "l"(a), "l"(b), "l"(d));
}
__device__ __forceinline__ float2 unpack2(u64 a) {
    float2 r; asm("mov.b64 {%0, %1}, %2;" : "=f"(r.x), "=f"(r.y) : "l"(a)); return r;
}
__device__ __forceinline__ float fast_sig(float x) {
    return __fdividef(1.f, 1.f + __expf(-x));
}
__device__ __forceinline__ float fast_tanh(float x) {
    return 2.f * fast_sig(2.f * x) - 1.f;
}

// ---------------- bf16 split helpers ----------------
__device__ __forceinline__ uint32_t pack_bf16(float x, float y) {
    __nv_bfloat162 t = __floats2bfloat162_rn(x, y);
    return *(uint32_t*)&t;
}
__device__ __forceinline__ void split4(float4 v, uint2& hi, uint2& mid) {
    __nv_bfloat162 h01 = __floats2bfloat162_rn(v.x, v.y);
    __nv_bfloat162 h23 = __floats2bfloat162_rn(v.z, v.w);
    float2 f01 = __bfloat1622float2(h01);
    float2 f23 = __bfloat1622float2(h23);
    hi.x  = *(uint32_t*)&h01;
    hi.y  = *(uint32_t*)&h23;
    mid.x = pack_bf16(v.x - f01.x, v.y - f01.y);
    mid.y = pack_bf16(v.z - f23.x, v.w - f23.y);
}
__device__ __forceinline__ void mma_bf16(float& c0, float& c1, float& c2, float& c3,
                                         uint32_t a0, uint32_t a1, uint32_t a2, uint32_t a3,
                                         uint32_t b0, uint32_t b1) {
    asm volatile(
        "mma.sync.aligned.m16n8k16.row.col.f32.bf16.bf16.f32 "
        "{%0,%1,%2,%3}, {%4,%5,%6,%7}, {%8,%9}, {%0,%1,%2,%3};"
        : "+f"(c0), "+f"(c1), "+f"(c2), "+f"(c3)
        : "r"(a0), "r"(a1), "r"(a2), "r"(a3), "r"(b0), "r"(b1));
}

// =================================================================
// 3xBF16 tensor-core GEMM v2: CTA 128x128, 512 THREADS (16 warps,
// 4/SMSP), warp tile m32n32, m16n8k16 x3, double-buffered smem.
// Same smem layout/swizzle as round 13 (validated). K chunks of 32.
// =================================================================
#define KC 32
#define STG_W  8192        // words per stage
#define OFF_AM 2048
#define OFF_WH 4096
#define OFF_WM 6144

__global__ __launch_bounds__(512, 1)
void gemm_tc_kernel(const float* __restrict__ A, const float* __restrict__ W,
                    const float* __restrict__ ba, const float* __restrict__ bb,
                    float* __restrict__ C, int M, int N, int K, int mapA)
{
    extern __shared__ __align__(16) uint32_t smw[];   // 2 * STG_W words

    const int tid = threadIdx.x;
    const int wid = tid >> 5;
    const int lid = tid & 31;
    const int bn  = blockIdx.x * 128;
    const int bm  = blockIdx.y * 128;

    const int m0w = (wid >> 2) * 32;   // 4 row-warps
    const int n0w = (wid & 3) * 32;    // 4 col-warps
    const int g   = lid >> 2;          // 0..7
    const int tig = lid & 3;           // 0..3
    const int xm  = g << 1;            // swizzle mask for fragment reads

    // ---- loader maps: idx = j*512+tid; row = idx>>3 (0..127), kq = idx&7 ----
    const float* aptr[2]; const float* wptr[2];
    int sl[2];
#pragma unroll
    for (int j = 0; j < 2; j++) {
        int idx = j * 512 + tid;
        int row = idx >> 3, kq = idx & 7;
        int m = bm + row;
        long ar = mapA ? ((long)(m & 63) * SS + (m >> 6)) : (long)m;
        aptr[j] = A + ar * K + kq * 4;
        wptr[j] = W + (long)(bn + row) * K + kq * 4;
        sl[j] = row * 16 + ((2 * kq) ^ ((row & 7) << 1));
    }

    // fragment row bases (word units)
    int rA0[2], rA1[2], rB[4];
#pragma unroll
    for (int i = 0; i < 2; i++) {
        rA0[i] = (m0w + 16 * i + g) * 16;
        rA1[i] = rA0[i] + 128;             // +8 rows
    }
#pragma unroll
    for (int j = 0; j < 4; j++)
        rB[j] = (n0w + 8 * j + g) * 16;

    float c[2][4][4];
#pragma unroll
    for (int i = 0; i < 2; i++)
#pragma unroll
        for (int j = 0; j < 4; j++)
#pragma unroll
            for (int r = 0; r < 4; r++) c[i][j][r] = 0.f;

    const int nc = K / KC;

    // ---- prologue: stage chunk 0 ----
    {
        uint32_t* sb = smw;
#pragma unroll
        for (int j = 0; j < 2; j++) {
            uint2 hi, mid;
            split4(__ldg((const float4*)aptr[j]), hi, mid);
            *(uint2*)&sb[sl[j]]          = hi;
            *(uint2*)&sb[OFF_AM + sl[j]] = mid;
            split4(__ldg((const float4*)wptr[j]), hi, mid);
            *(uint2*)&sb[OFF_WH + sl[j]] = hi;
            *(uint2*)&sb[OFF_WM + sl[j]] = mid;
        }
    }
    __syncthreads();

    for (int cc = 0; cc < nc; cc++) {
        const bool more = (cc + 1) < nc;

        float4 pa[2], pw[2];
        if (more) {
            int ko = (cc + 1) * KC;
#pragma unroll
            for (int j = 0; j < 2; j++) {
                pa[j] = __ldg((const float4*)(aptr[j] + ko));
                pw[j] = __ldg((const float4*)(wptr[j] + ko));
            }
        }

        const uint32_t* sb = smw + (cc & 1) * STG_W;
#pragma unroll
        for (int blk = 0; blk < 2; blk++) {
            const int cbase = 8 * blk;
            const int w0 = (tig + cbase) ^ xm;
            const int w4 = (tig + 4 + cbase) ^ xm;

            uint32_t ah[2][4], am[2][4];
#pragma unroll
            for (int i = 0; i < 2; i++) {
                ah[i][0] = sb[rA0[i] + w0];  ah[i][1] = sb[rA1[i] + w0];
                ah[i][2] = sb[rA0[i] + w4];  ah[i][3] = sb[rA1[i] + w4];
                am[i][0] = sb[OFF_AM + rA0[i] + w0];  am[i][1] = sb[OFF_AM + rA1[i] + w0];
                am[i][2] = sb[OFF_AM + rA0[i] + w4];  am[i][3] = sb[OFF_AM + rA1[i] + w4];
            }
            uint32_t bh[4][2], bmf[4][2];
#pragma unroll
            for (int j = 0; j < 4; j++) {
                bh[j][0]  = sb[OFF_WH + rB[j] + w0];  bh[j][1]  = sb[OFF_WH + rB[j] + w4];
                bmf[j][0] = sb[OFF_WM + rB[j] + w0];  bmf[j][1] = sb[OFF_WM + rB[j] + w4];
            }
#pragma unroll
            for (int i = 0; i < 2; i++)
#pragma unroll
                for (int j = 0; j < 4; j++) {
                    mma_bf16(c[i][j][0], c[i][j][1], c[i][j][2], c[i][j][3],
                             ah[i][0], ah[i][1], ah[i][2], ah[i][3],
                             bh[j][0], bh[j][1]);
                    mma_bf16(c[i][j][0], c[i][j][1], c[i][j][2], c[i][j][3],
                             ah[i][0], ah[i][1], ah[i][2], ah[i][3],
                             bmf[j][0], bmf[j][1]);
                    mma_bf16(c[i][j][0], c[i][j][1], c[i][j][2], c[i][j][3],
                             am[i][0], am[i][1], am[i][2], am[i][3],
                             bh[j][0], bh[j][1]);
                }
        }

        if (more) {
            uint32_t* nb = smw + ((cc + 1) & 1) * STG_W;
#pragma unroll
            for (int j = 0; j < 2; j++) {
                uint2 hi, mid;
                split4(pa[j], hi, mid);
                *(uint2*)&nb[sl[j]]          = hi;
                *(uint2*)&nb[OFF_AM + sl[j]] = mid;
                split4(pw[j], hi, mid);
                *(uint2*)&nb[OFF_WH + sl[j]] = hi;
                *(uint2*)&nb[OFF_WM + sl[j]] = mid;
            }
            __syncthreads();
        }
    }

    // ---- epilogue: bias + store ----
#pragma unroll
    for (int j = 0; j < 4; j++) {
        int n = bn + n0w + 8 * j + 2 * tig;
        float2 bv = *(const float2*)&ba[n];
        if (bb) {
            float2 b2 = *(const float2*)&bb[n];
            bv.x += b2.x; bv.y += b2.y;
        }
#pragma unroll
        for (int i = 0; i < 2; i++) {
            long m0 = bm + m0w + 16 * i + g;
            long m1 = m0 + 8;
            float2 o0 = {c[i][j][0] + bv.x, c[i][j][1] + bv.y};
            float2 o1 = {c[i][j][2] + bv.x, c[i][j][3] + bv.y};
            *(float2*)&C[m0 * N + n] = o0;
            *(float2*)&C[m1 * N + n] = o1;
        }
    }
}

// ---------------------------------------------------------------
// Persistent LSTM layer kernel (round-7 best configuration, unchanged).
// ---------------------------------------------------------------
__global__ __launch_bounds__(256, 1)
void lstm_layer_kernel(const float* __restrict__ xg,    // [S][64][4096]
                       const float* __restrict__ Whh,   // [4096][1024]
                       float* __restrict__ h,           // [2][64][1024]
                       float* __restrict__ y,           // [B][S][H]
                       float* __restrict__ out_h,
                       float* __restrict__ out_c)
{
    extern __shared__ float lsm[];
    float* Wall = lsm;                           // 32*1024 floats, swizzled
    float* HsF  = lsm + 32 * 1024;               // 64 rows * 33 float4
    float* Pm   = HsF + 64 * 132;                // 64*33
    float* Cs   = Pm + 64 * 33;                  // 512

    float4*     Hs4 = (float4*)HsF;
    ulonglong2* HsU = (ulonglong2*)HsF;

    const int tid = threadIdx.x;
    const int j0  = blockIdx.x * 8;
    const int tx  = tid & 15;
    const int ty  = tid >> 4;
    const int c0  = tx * 2;
    const int r0  = ty * 4;
    const int swz = tx & 7;

    int soff[8];
    int sslot[8];
#pragma unroll
    for (int i = 0; i < 8; i++) {
        int idx = i * 256 + tid;
        int row = idx >> 5, kc = idx & 31;
        soff[i]  = row * HH + kc * 4;
        sslot[i] = row * 33 + kc;
    }

    {
        float4 z = make_float4(0.f, 0.f, 0.f, 0.f);
        *(float4*)&h[blockIdx.x * 1024 + tid * 4] = z;
        Cs[tid]       = 0.f;
        Cs[tid + 256] = 0.f;
    }
#pragma unroll 4
    for (int i = 0; i < 32; i++) {
        int idx = i * 256 + tid;
        int wr = idx >> 8;
        int kq = idx & 255;
        int grow = (wr >> 3) * HH + j0 + (wr & 7);
        float4 v = *(const float4*)(Whh + (long)grow * HH + kq * 4);
        int slot = kq ^ ((wr >> 1) & 7);
        *(float4*)&Wall[wr * 1024 + slot * 4] = v;
    }

    unsigned nbar = 0;
    __syncthreads();
    nbar++;
    if (tid == 0) {
        __threadfence();
        atomicAdd(&g_bar, 1u);
        while (*(volatile unsigned*)&g_bar < nbar * NBLK) { }
    }
    __syncthreads();

    const ulonglong2* Wp0 = (const ulonglong2*)&Wall[c0 * 1024];
    const ulonglong2* Wp1 = (const ulonglong2*)&Wall[(c0 + 1) * 1024];

    for (int t = 0; t < SS; t++) {
        const float* h_in  = h + (size_t)(t & 1) * BH;
        float*       h_out = h + (size_t)((t + 1) & 1) * BH;
        const float* xg_t  = xg + (size_t)t * BB * G4;

        const int gate = c0 >> 3;
        const int jl0  = c0 & 7;
        float2 xv[4];
#pragma unroll
        for (int r = 0; r < 4; r++)
            xv[r] = *(const float2*)(xg_t + (long)(r0 + r) * G4 + gate * HH + j0 + jl0);

        u64 acc[4][2];
#pragma unroll
        for (int r = 0; r < 4; r++) { acc[r][0] = 0ull; acc[r][1] = 0ull; }

        float4 pf[8];
#pragma unroll
        for (int i = 0; i < 8; i++)
            pf[i] = __ldcg((const float4*)(h_in + soff[i]));

#pragma unroll 1
        for (int cc = 0; cc < 8; cc++) {
            __syncthreads();
#pragma unroll
            for (int i = 0; i < 8; i++) Hs4[sslot[i]] = pf[i];
            __syncthreads();
            if (cc < 7) {
#pragma unroll
                for (int i = 0; i < 8; i++)
                    pf[i] = __ldcg((const float4*)(h_in + soff[i] + (cc + 1) * 128));
            }

            const int kqb = cc * 32;
#pragma unroll 4
            for (int kql = 0; kql < 32; kql++) {
                int s = (kqb + kql) ^ swz;
                ulonglong2 w0 = Wp0[s];
                ulonglong2 w1 = Wp1[s];
#pragma unroll
                for (int r = 0; r < 4; r++) {
                    ulonglong2 hv = HsU[(r0 + r) * 33 + kql];
                    fma2(acc[r][0], hv.x, w0.x);
                    fma2(acc[r][0], hv.y, w0.y);
                    fma2(acc[r][1], hv.x, w1.x);
                    fma2(acc[r][1], hv.y, w1.y);
                }
            }
        }

#pragma unroll
        for (int r = 0; r < 4; r++) {
            int b = r0 + r;
            float2 u0 = unpack2(acc[r][0]);
            float2 u1 = unpack2(acc[r][1]);
            Pm[b * 33 + c0]     = u0.x + u0.y + xv[r].x;
            Pm[b * 33 + c0 + 1] = u1.x + u1.y + xv[r].y;
        }
        __syncthreads();

#pragma unroll
        for (int pi = 0; pi < 2; pi++) {
            int p  = tid + pi * 256;
            int b  = p >> 3;
            int jl = p & 7;
            int j  = j0 + jl;
            float iv = fast_sig (Pm[b * 33 + 0  + jl]);
            float fv = fast_sig (Pm[b * 33 + 8  + jl]);
            float gv = fast_tanh(Pm[b * 33 + 16 + jl]);
            float ov = fast_sig (Pm[b * 33 + 24 + jl]);
            float cn = fv * Cs[b * 8 + jl] + iv * gv;
            Cs[b * 8 + jl] = cn;
            float hn = ov * fast_tanh(cn);
            __stcg(h_out + (long)b * HH + j, hn);
            y[((long)b * SS + t) * HH + j] = hn;
            if (t == SS - 1) {
                out_h[(long)b * HH + j] = hn;
                out_c[(long)b * HH + j] = cn;
            }
        }

        __threadfence();
        __syncthreads();
        nbar++;
        if (tid == 0) {
            atomicAdd(&g_bar, 1u);
            while (*(volatile unsigned*)&g_bar < nbar * NBLK) { }
            __threadfence();
        }
        __syncthreads();
    }
}

extern "C" void kernel_launch(void* const* d_in, const int* in_sizes, int n_in,
                              void* d_out, int out_size)
{
    const float* x     = (const float*)d_in[0];
    const float* W_ih0 = (const float*)d_in[1];
    const float* W_hh0 = (const float*)d_in[2];
    const float* b_ih0 = (const float*)d_in[3];
    const float* b_hh0 = (const float*)d_in[4];
    const float* W_ih1 = (const float*)d_in[5];
    const float* W_hh1 = (const float*)d_in[6];
    const float* b_ih1 = (const float*)d_in[7];
    const float* b_hh1 = (const float*)d_in[8];
    const float* W_fc  = (const float*)d_in[9];
    const float* b_fc  = (const float*)d_in[10];
    float* out = (float*)d_out;

    float *xg, *y, *h;
    unsigned* bar;
    cudaGetSymbolAddress((void**)&xg,  g_xg);
    cudaGetSymbolAddress((void**)&y,   g_y);
    cudaGetSymbolAddress((void**)&h,   g_h);
    cudaGetSymbolAddress((void**)&bar, g_bar);

    const int SMEM_LAYER = (32 * 1024 + 64 * 132 + 64 * 33 + 512) * 4;  // 175,360
    cudaFuncSetAttribute(lstm_layer_kernel,
                         cudaFuncAttributeMaxDynamicSharedMemorySize, SMEM_LAYER);
    const int SMEM_TC = 2 * STG_W * 4;                                  // 65,536
    cudaFuncSetAttribute(gemm_tc_kernel,
                         cudaFuncAttributeMaxDynamicSharedMemorySize, SMEM_TC);

    const int M = SS * BB;  // 32768

    // ---------------- layer 0 ----------------
    gemm_tc_kernel<<<dim3(G4 / 128, M / 128), 512, SMEM_TC>>>(
        x, W_ih0, b_ih0, b_hh0, xg, M, G4, II, 1);
    cudaMemsetAsync(bar, 0, sizeof(unsigned));
    lstm_layer_kernel<<<NBLK, 256, SMEM_LAYER>>>(
        xg, W_hh0, h, y,
        out + OUT_ELEMS,
        out + OUT_ELEMS + 2 * BH);

    // ---------------- layer 1 ----------------
    gemm_tc_kernel<<<dim3(G4 / 128, M / 128), 512, SMEM_TC>>>(
        y, W_ih1, b_ih1, b_hh1, xg, M, G4, HH, 1);
    cudaMemsetAsync(bar, 0, sizeof(unsigned));
    lstm_layer_kernel<<<NBLK, 256, SMEM_LAYER>>>(
        xg, W_hh1, h, y,
        out + OUT_ELEMS + BH,
        out + OUT_ELEMS + 3 * BH);

    // ---------------- FC ----------------
    gemm_tc_kernel<<<dim3(OO / 128, M / 128), 512, SMEM_TC>>>(
        y, W_fc, b_fc, nullptr, out, M, OO, HH, 0);
}

// round 17
// speedup vs baseline: 1.6777x; 1.6777x over previous
#include <cuda_runtime.h>
#include <cuda_bf16.h>
#include <math.h>
#include <stdint.h>

#define BB   64
#define SS   512
#define II   512
#define HH   1024
#define G4   4096
#define OO   512
#define BH   (BB*HH)          // 65536
#define OUT_ELEMS (BB*SS*OO)  // 16777216
#define NBLK 128

typedef unsigned long long u64;

// -------- scratch (device globals) --------
__device__ float    g_xg[(size_t)SS * BB * G4];   // 512 MB
__device__ float    g_y [(size_t)BB * SS * HH];   // 128 MB
__device__ uint32_t g_hbf[2][2][BB * (HH / 2)];   // [parity][hi/mid][64*512 words]
__device__ unsigned g_bar;

__device__ __forceinline__ float fast_sig(float x) {
    return __fdividef(1.f, 1.f + __expf(-x));
}
__device__ __forceinline__ float fast_tanh(float x) {
    return 2.f * fast_sig(2.f * x) - 1.f;
}

// ---------------- bf16 split helpers ----------------
__device__ __forceinline__ uint32_t pack_bf16(float x, float y) {
    __nv_bfloat162 t = __floats2bfloat162_rn(x, y);
    return *(uint32_t*)&t;
}
__device__ __forceinline__ void split4(float4 v, uint2& hi, uint2& mid) {
    __nv_bfloat162 h01 = __floats2bfloat162_rn(v.x, v.y);
    __nv_bfloat162 h23 = __floats2bfloat162_rn(v.z, v.w);
    float2 f01 = __bfloat1622float2(h01);
    float2 f23 = __bfloat1622float2(h23);
    hi.x  = *(uint32_t*)&h01;
    hi.y  = *(uint32_t*)&h23;
    mid.x = pack_bf16(v.x - f01.x, v.y - f01.y);
    mid.y = pack_bf16(v.z - f23.x, v.w - f23.y);
}
__device__ __forceinline__ void mma_bf16(float& c0, float& c1, float& c2, float& c3,
                                         uint32_t a0, uint32_t a1, uint32_t a2, uint32_t a3,
                                         uint32_t b0, uint32_t b1) {
    asm volatile(
        "mma.sync.aligned.m16n8k16.row.col.f32.bf16.bf16.f32 "
        "{%0,%1,%2,%3}, {%4,%5,%6,%7}, {%8,%9}, {%0,%1,%2,%3};"
        : "+f"(c0), "+f"(c1), "+f"(c2), "+f"(c3)
        : "r"(a0), "r"(a1), "r"(a2), "r"(a3), "r"(b0), "r"(b1));
}

// =================================================================
// 3xBF16 tensor-core GEMM (round-13, byte-identical).
// =================================================================
#define KC 32
#define STG_W  8192
#define OFF_AM 2048
#define OFF_WH 4096
#define OFF_WM 6144

__global__ __launch_bounds__(256, 1)
void gemm_tc_kernel(const float* __restrict__ A, const float* __restrict__ W,
                    const float* __restrict__ ba, const float* __restrict__ bb,
                    float* __restrict__ C, int M, int N, int K, int mapA)
{
    extern __shared__ __align__(16) uint32_t smw[];

    const int tid = threadIdx.x;
    const int wid = tid >> 5;
    const int lid = tid & 31;
    const int bn  = blockIdx.x * 128;
    const int bm  = blockIdx.y * 128;

    const int m0w = (wid >> 2) * 64;
    const int n0w = (wid & 3) * 32;
    const int g   = lid >> 2;
    const int tig = lid & 3;
    const int xm  = g << 1;

    const float* aptr[4]; const float* wptr[4];
    int sl[4];
#pragma unroll
    for (int j = 0; j < 4; j++) {
        int idx = j * 256 + tid;
        int row = idx >> 3, kq = idx & 7;
        int m = bm + row;
        long ar = mapA ? ((long)(m & 63) * SS + (m >> 6)) : (long)m;
        aptr[j] = A + ar * K + kq * 4;
        wptr[j] = W + (long)(bn + row) * K + kq * 4;
        sl[j] = row * 16 + ((2 * kq) ^ ((row & 7) << 1));
    }

    int rA0[4], rA1[4], rB[4];
#pragma unroll
    for (int i = 0; i < 4; i++) {
        rA0[i] = (m0w + 16 * i + g) * 16;
        rA1[i] = rA0[i] + 128;
        rB[i]  = (n0w + 8 * i + g) * 16;
    }

    float c[4][4][4];
#pragma unroll
    for (int i = 0; i < 4; i++)
#pragma unroll
        for (int j = 0; j < 4; j++)
#pragma unroll
            for (int r = 0; r < 4; r++) c[i][j][r] = 0.f;

    const int nc = K / KC;

    {
        uint32_t* sb = smw;
#pragma unroll
        for (int j = 0; j < 4; j++) {
            uint2 hi, mid;
            split4(__ldg((const float4*)aptr[j]), hi, mid);
            *(uint2*)&sb[sl[j]]          = hi;
            *(uint2*)&sb[OFF_AM + sl[j]] = mid;
            split4(__ldg((const float4*)wptr[j]), hi, mid);
            *(uint2*)&sb[OFF_WH + sl[j]] = hi;
            *(uint2*)&sb[OFF_WM + sl[j]] = mid;
        }
    }
    __syncthreads();

    for (int cc = 0; cc < nc; cc++) {
        const bool more = (cc + 1) < nc;
        float4 pa[4], pw[4];
        if (more) {
            int ko = (cc + 1) * KC;
#pragma unroll
            for (int j = 0; j < 4; j++) {
                pa[j] = __ldg((const float4*)(aptr[j] + ko));
                pw[j] = __ldg((const float4*)(wptr[j] + ko));
            }
        }

        const uint32_t* sb = smw + (cc & 1) * STG_W;
#pragma unroll
        for (int blk = 0; blk < 2; blk++) {
            const int cbase = 8 * blk;
            const int w0 = (tig + cbase) ^ xm;
            const int w4 = (tig + 4 + cbase) ^ xm;

            uint32_t ah[4][4], am[4][4];
#pragma unroll
            for (int i = 0; i < 4; i++) {
                ah[i][0] = sb[rA0[i] + w0];  ah[i][1] = sb[rA1[i] + w0];
                ah[i][2] = sb[rA0[i] + w4];  ah[i][3] = sb[rA1[i] + w4];
                am[i][0] = sb[OFF_AM + rA0[i] + w0];  am[i][1] = sb[OFF_AM + rA1[i] + w0];
                am[i][2] = sb[OFF_AM + rA0[i] + w4];  am[i][3] = sb[OFF_AM + rA1[i] + w4];
            }
            uint32_t bh[4][2], bmf[4][2];
#pragma unroll
            for (int j = 0; j < 4; j++) {
                bh[j][0]  = sb[OFF_WH + rB[j] + w0];  bh[j][1]  = sb[OFF_WH + rB[j] + w4];
                bmf[j][0] = sb[OFF_WM + rB[j] + w0];  bmf[j][1] = sb[OFF_WM + rB[j] + w4];
            }
#pragma unroll
            for (int i = 0; i < 4; i++)
#pragma unroll
                for (int j = 0; j < 4; j++) {
                    mma_bf16(c[i][j][0], c[i][j][1], c[i][j][2], c[i][j][3],
                             ah[i][0], ah[i][1], ah[i][2], ah[i][3],
                             bh[j][0], bh[j][1]);
                    mma_bf16(c[i][j][0], c[i][j][1], c[i][j][2], c[i][j][3],
                             ah[i][0], ah[i][1], ah[i][2], ah[i][3],
                             bmf[j][0], bmf[j][1]);
                    mma_bf16(c[i][j][0], c[i][j][1], c[i][j][2], c[i][j][3],
                             am[i][0], am[i][1], am[i][2], am[i][3],
                             bh[j][0], bh[j][1]);
                }
        }

        if (more) {
            uint32_t* nb = smw + ((cc + 1) & 1) * STG_W;
#pragma unroll
            for (int j = 0; j < 4; j++) {
                uint2 hi, mid;
                split4(pa[j], hi, mid);
                *(uint2*)&nb[sl[j]]          = hi;
                *(uint2*)&nb[OFF_AM + sl[j]] = mid;
                split4(pw[j], hi, mid);
                *(uint2*)&nb[OFF_WH + sl[j]] = hi;
                *(uint2*)&nb[OFF_WM + sl[j]] = mid;
            }
            __syncthreads();
        }
    }

#pragma unroll
    for (int j = 0; j < 4; j++) {
        int n = bn + n0w + 8 * j + 2 * tig;
        float2 bv = *(const float2*)&ba[n];
        if (bb) {
            float2 b2 = *(const float2*)&bb[n];
            bv.x += b2.x; bv.y += b2.y;
        }
#pragma unroll
        for (int i = 0; i < 4; i++) {
            long m0 = bm + m0w + 16 * i + g;
            long m1 = m0 + 8;
            float2 o0 = {c[i][j][0] + bv.x, c[i][j][1] + bv.y};
            float2 o1 = {c[i][j][2] + bv.x, c[i][j][3] + bv.y};
            *(float2*)&C[m0 * N + n] = o0;
            *(float2*)&C[m1 * N + n] = o1;
        }
    }
}

// =================================================================
// Persistent LSTM layer kernel v3: MMA recurrence.
// 128 blocks x 256 threads, 512 steps, grid barrier.
// Per block: 8 hidden units x 4 gates = 32 W rows. W_hh pre-split
// (bf16 hi/mid) resident in smem (128 KB). h carried as packed bf16
// hi/mid global buffers (written by previous step's epilogue).
// Per step: M64 x N32 x K1024 via m16n8k16 x3 (hi*hi + hi*mid + mid*hi).
// Warp tiling: 8 warps, warp = m16 x n16 (mt = wid>>1, nh = wid&1).
// smem words: W 32768 + A 2x4096 + (Pm 64x34 floats).
// =================================================================
__global__ __launch_bounds__(256, 1)
void lstm_layer_kernel(const float* __restrict__ xg,    // [S][64][4096]
                       const float* __restrict__ Whh,   // [4096][1024]
                       uint32_t* __restrict__ hbf,      // [2][2][64*512]
                       float* __restrict__ y,           // [B][S][H]
                       float* __restrict__ out_h,
                       float* __restrict__ out_c)
{
    extern __shared__ __align__(16) uint32_t smw[];
    // layout: Wsm [32 subchunks][ hi 32x16 | mid 32x16 ] = 32768 words
    //         Asm [2 groups][2 subchunks][ hi 64x16 | mid 64x16 ] = 8192 words
    //         Pm  (floats) 64 x 34
    uint32_t* Wsm = smw;
    uint32_t* Asm = smw + 32768;
    float*    Pm  = (float*)(smw + 32768 + 8192);

    const int tid = threadIdx.x;
    const int wid = tid >> 5;
    const int lid = tid & 31;
    const int j0  = blockIdx.x * 8;

    const int mt  = wid >> 1;          // m-tile 0..3 (batch rows 16*mt..)
    const int nh  = wid & 1;           // n-half (cols 16*nh..)
    const int g   = lid >> 2;
    const int tig = lid & 3;
    const int xm  = g << 1;

    const int rA0 = (16 * mt + g) * 16;       // within A hi region
    const int rB0 = (16 * nh + g) * 16;       // atom 0 row base (within W hi)
    const int rB1 = (16 * nh + 8 + g) * 16;   // atom 1

    // staging map: row = tid>>2 (0..63), q = tid&3 (uint4 index 0..3)
    const int srow = tid >> 2;
    const int sq   = tid & 3;
    const int ssh  = (srow & 7) << 1;
    const int sslot0 = srow * 16 + ((4 * sq)     ^ ssh);
    const int sslot1 = srow * 16 + ((4 * sq + 2) ^ ssh);
    const int goff   = srow * 512 + sq * 4;    // global word offset within h buffer

    // epilogue map: b = tid>>2, jj = (tid&3)*2
    const int eb  = tid >> 2;
    const int ejj = (tid & 3) * 2;

    // ---- prologue: zero h parity-0 buffers; pre-split W into smem ----
    {
        int gid = blockIdx.x * 256 + tid;          // 0..32767
        uint2 z = {0u, 0u};
        *(uint2*)&hbf[0 * 2 * 32768 + 0 * 32768 + gid * 2 - gid * 2 + 2 * gid] = z; // hi
        // (write hi words 2*gid, 2*gid+1)
        *(uint2*)&hbf[32768 + 2 * gid] = z;        // mid words
    }
#pragma unroll 4
    for (int i = 0; i < 32; i++) {
        int idx = i * 256 + tid;
        int wr  = idx >> 8;            // W row 0..31
        int kq8 = idx & 255;           // float4 index along K
        int cs  = kq8 >> 3;            // subchunk 0..31
        int kq  = kq8 & 7;
        int grow = (wr >> 3) * HH + j0 + (wr & 7);
        float4 v = *(const float4*)(Whh + (long)grow * HH + kq8 * 4);
        int slot = cs * 1024 + wr * 16 + ((2 * kq) ^ ((wr & 7) << 1));
        uint2 hi, mid;
        split4(v, hi, mid);
        *(uint2*)&Wsm[slot]       = hi;
        *(uint2*)&Wsm[slot + 512] = mid;
    }

    float creg0 = 0.f, creg1 = 0.f;    // this thread's cell state (b=eb, j=j0+ejj(+1))

    unsigned nbar = 0;
    __syncthreads();
    nbar++;
    if (tid == 0) {
        __threadfence();
        atomicAdd(&g_bar, 1u);
        while (*(volatile unsigned*)&g_bar < nbar * NBLK) { }
    }
    __syncthreads();

    for (int t = 0; t < SS; t++) {
        const uint32_t* hin_hi  = hbf + (size_t)(t & 1) * 65536;
        const uint32_t* hin_mid = hin_hi + 32768;
        uint32_t* hout_hi  = hbf + (size_t)((t + 1) & 1) * 65536;
        uint32_t* hout_mid = hout_hi + 32768;
        const float* xg_t = xg + (size_t)t * BB * G4;

        float c0[4], c1[4];            // atom0 / atom1 accumulators
#pragma unroll
        for (int r = 0; r < 4; r++) { c0[r] = 0.f; c1[r] = 0.f; }

        // prefetch group 0 (subchunks 0,1): hi+mid uint4 each
        uint4 pfh[2], pfm[2];
#pragma unroll
        for (int s = 0; s < 2; s++) {
            pfh[s] = __ldg((const uint4*)(hin_hi  + goff + s * 16));
            pfm[s] = __ldg((const uint4*)(hin_mid + goff + s * 16));
        }

#pragma unroll 1
        for (int gi = 0; gi < 16; gi++) {
            uint32_t* ab = Asm + (gi & 1) * 4096;
#pragma unroll
            for (int s = 0; s < 2; s++) {
                uint32_t* hb = ab + s * 2048;
                *(uint2*)&hb[sslot0] = make_uint2(pfh[s].x, pfh[s].y);
                *(uint2*)&hb[sslot1] = make_uint2(pfh[s].z, pfh[s].w);
                *(uint2*)&hb[1024 + sslot0] = make_uint2(pfm[s].x, pfm[s].y);
                *(uint2*)&hb[1024 + sslot1] = make_uint2(pfm[s].z, pfm[s].w);
            }
            __syncthreads();
            if (gi < 15) {
                int kb = (gi + 1) * 32;   // word offset of next group
#pragma unroll
                for (int s = 0; s < 2; s++) {
                    pfh[s] = __ldg((const uint4*)(hin_hi  + goff + kb + s * 16));
                    pfm[s] = __ldg((const uint4*)(hin_mid + goff + kb + s * 16));
                }
            }

#pragma unroll
            for (int s = 0; s < 2; s++) {
                const uint32_t* Ah = ab + s * 2048;
                const uint32_t* Am = Ah + 1024;
                const uint32_t* Wh = Wsm + (gi * 2 + s) * 1024;
                const uint32_t* Wm = Wh + 512;
#pragma unroll
                for (int blk = 0; blk < 2; blk++) {
                    const int cbase = 8 * blk;
                    const int w0 = (tig + cbase) ^ xm;
                    const int w4 = (tig + 4 + cbase) ^ xm;

                    uint32_t ah0 = Ah[rA0 + w0];
                    uint32_t ah1 = Ah[rA0 + 128 + w0];
                    uint32_t ah2 = Ah[rA0 + w4];
                    uint32_t ah3 = Ah[rA0 + 128 + w4];
                    uint32_t am0 = Am[rA0 + w0];
                    uint32_t am1 = Am[rA0 + 128 + w0];
                    uint32_t am2 = Am[rA0 + w4];
                    uint32_t am3 = Am[rA0 + 128 + w4];

                    uint32_t b0h0 = Wh[rB0 + w0], b0h1 = Wh[rB0 + w4];
                    uint32_t b0m0 = Wm[rB0 + w0], b0m1 = Wm[rB0 + w4];
                    uint32_t b1h0 = Wh[rB1 + w0], b1h1 = Wh[rB1 + w4];
                    uint32_t b1m0 = Wm[rB1 + w0], b1m1 = Wm[rB1 + w4];

                    mma_bf16(c0[0], c0[1], c0[2], c0[3], ah0, ah1, ah2, ah3, b0h0, b0h1);
                    mma_bf16(c1[0], c1[1], c1[2], c1[3], ah0, ah1, ah2, ah3, b1h0, b1h1);
                    mma_bf16(c0[0], c0[1], c0[2], c0[3], ah0, ah1, ah2, ah3, b0m0, b0m1);
                    mma_bf16(c1[0], c1[1], c1[2], c1[3], ah0, ah1, ah2, ah3, b1m0, b1m1);
                    mma_bf16(c0[0], c0[1], c0[2], c0[3], am0, am1, am2, am3, b0h0, b0h1);
                    mma_bf16(c1[0], c1[1], c1[2], c1[3], am0, am1, am2, am3, b1h0, b1h1);
                }
            }
        }

        // ---- stash pre-activations to Pm ----
        {
            int prow0 = 16 * mt + g;
            int prow1 = prow0 + 8;
            int col0 = 16 * nh + 2 * tig;
            int col1 = col0 + 8;
            *(float2*)&Pm[prow0 * 34 + col0] = make_float2(c0[0], c0[1]);
            *(float2*)&Pm[prow1 * 34 + col0] = make_float2(c0[2], c0[3]);
            *(float2*)&Pm[prow0 * 34 + col1] = make_float2(c1[0], c1[1]);
            *(float2*)&Pm[prow1 * 34 + col1] = make_float2(c1[2], c1[3]);
        }
        __syncthreads();

        // ---- gate math: thread -> (b=eb, hidden j0+ejj, j0+ejj+1) ----
        {
            const float* xb = xg_t + (long)eb * G4 + j0 + ejj;
            float2 xi = *(const float2*)(xb);
            float2 xf = *(const float2*)(xb + HH);
            float2 xgv = *(const float2*)(xb + 2 * HH);
            float2 xo = *(const float2*)(xb + 3 * HH);

            float iv0 = fast_sig (Pm[eb * 34 + 0  + ejj]     + xi.x);
            float iv1 = fast_sig (Pm[eb * 34 + 0  + ejj + 1] + xi.y);
            float fv0 = fast_sig (Pm[eb * 34 + 8  + ejj]     + xf.x);
            float fv1 = fast_sig (Pm[eb * 34 + 8  + ejj + 1] + xf.y);
            float gv0 = fast_tanh(Pm[eb * 34 + 16 + ejj]     + xgv.x);
            float gv1 = fast_tanh(Pm[eb * 34 + 16 + ejj + 1] + xgv.y);
            float ov0 = fast_sig (Pm[eb * 34 + 24 + ejj]     + xo.x);
            float ov1 = fast_sig (Pm[eb * 34 + 24 + ejj + 1] + xo.y);

            creg0 = fv0 * creg0 + iv0 * gv0;
            creg1 = fv1 * creg1 + iv1 * gv1;
            float hn0 = ov0 * fast_tanh(creg0);
            float hn1 = ov1 * fast_tanh(creg1);

            // packed bf16 hi/mid h write
            __nv_bfloat162 hh = __floats2bfloat162_rn(hn0, hn1);
            float2 hf = __bfloat1622float2(hh);
            uint32_t hiw = *(uint32_t*)&hh;
            uint32_t miw = pack_bf16(hn0 - hf.x, hn1 - hf.y);
            int hword = eb * 512 + (j0 + ejj) / 2;
            hout_hi[hword]  = hiw;
            hout_mid[hword] = miw;

            *(float2*)&y[((long)eb * SS + t) * HH + j0 + ejj] = make_float2(hn0, hn1);
            if (t == SS - 1) {
                *(float2*)&out_h[(long)eb * HH + j0 + ejj] = make_float2(hn0, hn1);
                *(float2*)&out_c[(long)eb * HH + j0 + ejj] = make_float2(creg0, creg1);
            }
        }

        // grid barrier
        __threadfence();
        __syncthreads();
        nbar++;
        if (tid == 0) {
            atomicAdd(&g_bar, 1u);
            while (*(volatile unsigned*)&g_bar < nbar * NBLK) { }
            __threadfence();
        }
        __syncthreads();
    }
}

extern "C" void kernel_launch(void* const* d_in, const int* in_sizes, int n_in,
                              void* d_out, int out_size)
{
    const float* x     = (const float*)d_in[0];
    const float* W_ih0 = (const float*)d_in[1];
    const float* W_hh0 = (const float*)d_in[2];
    const float* b_ih0 = (const float*)d_in[3];
    const float* b_hh0 = (const float*)d_in[4];
    const float* W_ih1 = (const float*)d_in[5];
    const float* W_hh1 = (const float*)d_in[6];
    const float* b_ih1 = (const float*)d_in[7];
    const float* b_hh1 = (const float*)d_in[8];
    const float* W_fc  = (const float*)d_in[9];
    const float* b_fc  = (const float*)d_in[10];
    float* out = (float*)d_out;

    float *xg, *y;
    uint32_t* hbf;
    unsigned* bar;
    cudaGetSymbolAddress((void**)&xg,  g_xg);
    cudaGetSymbolAddress((void**)&y,   g_y);
    cudaGetSymbolAddress((void**)&hbf, g_hbf);
    cudaGetSymbolAddress((void**)&bar, g_bar);

    const int SMEM_LSTM = (32768 + 8192) * 4 + 64 * 34 * 4;   // 172,544 B
    cudaFuncSetAttribute(lstm_layer_kernel,
                         cudaFuncAttributeMaxDynamicSharedMemorySize, SMEM_LSTM);
    const int SMEM_TC = 2 * STG_W * 4;                        // 65,536
    cudaFuncSetAttribute(gemm_tc_kernel,
                         cudaFuncAttributeMaxDynamicSharedMemorySize, SMEM_TC);

    const int M = SS * BB;  // 32768

    // ---------------- layer 0 ----------------
    gemm_tc_kernel<<<dim3(G4 / 128, M / 128), 256, SMEM_TC>>>(
        x, W_ih0, b_ih0, b_hh0, xg, M, G4, II, 1);
    cudaMemsetAsync(bar, 0, sizeof(unsigned));
    lstm_layer_kernel<<<NBLK, 256, SMEM_LSTM>>>(
        xg, W_hh0, hbf, y,
        out + OUT_ELEMS,
        out + OUT_ELEMS + 2 * BH);

    // ---------------- layer 1 ----------------
    gemm_tc_kernel<<<dim3(G4 / 128, M / 128), 256, SMEM_TC>>>(
        y, W_ih1, b_ih1, b_hh1, xg, M, G4, HH, 1);
    cudaMemsetAsync(bar, 0, sizeof(unsigned));
    lstm_layer_kernel<<<NBLK, 256, SMEM_LSTM>>>(
        xg, W_hh1, hbf, y,
        out + OUT_ELEMS + BH,
        out + OUT_ELEMS + 3 * BH);

    // ---------------- FC ----------------
    gemm_tc_kernel<<<dim3(OO / 128, M / 128), 256, SMEM_TC>>>(
        y, W_fc, b_fc, nullptr, out, M, OO, HH, 0);
}